// round 1
// baseline (speedup 1.0000x reference)
#include <cuda_runtime.h>

// Rz_layer: out = exp(-0.5i * phase(block, d)) * (re + i*im)
//   phase(block, d) = sum_q w[block][q] * (1 - 2*bit_q(d)),  bit_q = (d >> (NQ-1-q)) & 1
//   out_real = c*re + s*im ;  out_imag = c*im - s*re   (c = cos(h), s = sin(h), h = 0.5*phase)
//
// Shapes: state (256, 32, 2, 4096) fp32; weights (32, 12) fp32.
// Output: (2, 256, 32, 2, 4096) fp32  -> real plane then imag plane.

#define NQ       12
#define DIM      4096
#define NBLOCKS  32
#define DC       2
#define BATCH    256
#define TABLE    (NBLOCKS * DIM)            // 131072
#define NELEM    (BATCH * NBLOCKS * DC * DIM) // 67108864

// 1 MB of L2-resident rotation table (allowed: __device__ globals, no allocation)
__device__ float g_cos[TABLE];
__device__ float g_sin[TABLE];

// ---------------------------------------------------------------------------
// Kernel 1: build the per-(block, d) rotation table. 131072 threads, trivial.
// ---------------------------------------------------------------------------
__global__ void phase_table_kernel(const float* __restrict__ w) {
    int idx = blockIdx.x * blockDim.x + threadIdx.x;
    if (idx >= TABLE) return;
    int blk = idx >> 12;          // / DIM
    int d   = idx & (DIM - 1);

    float phase = 0.0f;
#pragma unroll
    for (int q = 0; q < NQ; q++) {
        // bit_q(d) = (d >> (NQ-1-q)) & 1 ; sign = 1 - 2*bit
        float sign = ((d >> (NQ - 1 - q)) & 1) ? -1.0f : 1.0f;
        phase = fmaf(__ldg(&w[blk * NQ + q]), sign, phase);
    }
    float h = 0.5f * phase;
    float s, c;
    sincosf(h, &s, &c);           // accurate variant; only 131K calls total
    g_cos[idx] = c;
    g_sin[idx] = s;
}

// ---------------------------------------------------------------------------
// Kernel 2: streaming complex rotation, float4-vectorized.
// Element layout (fp32 units): (((batch*32 + blk)*2 + dc)*4096 + d)
// In float4 units:  d4 = u & 1023 ; dc = (u>>10)&1 ; blk = (u>>11)&31
// Table float4 index: blk*1024 + d4   (L2-resident, 1 MB)
// ---------------------------------------------------------------------------
__global__ void __launch_bounds__(256)
apply_kernel(const float4* __restrict__ re,
             const float4* __restrict__ im,
             float4* __restrict__ out_re,
             float4* __restrict__ out_im) {
    int u = blockIdx.x * blockDim.x + threadIdx.x;   // float4 index, < NELEM/4

    int d4  = u & 1023;
    int blk = (u >> 11) & 31;
    int t   = (blk << 10) | d4;

    const float4* __restrict__ c_tab = reinterpret_cast<const float4*>(g_cos);
    const float4* __restrict__ s_tab = reinterpret_cast<const float4*>(g_sin);

    float4 c = __ldg(&c_tab[t]);
    float4 s = __ldg(&s_tab[t]);
    float4 r = re[u];
    float4 m = im[u];

    float4 orr, oii;
    orr.x = fmaf(c.x, r.x,  s.x * m.x);
    orr.y = fmaf(c.y, r.y,  s.y * m.y);
    orr.z = fmaf(c.z, r.z,  s.z * m.z);
    orr.w = fmaf(c.w, r.w,  s.w * m.w);
    oii.x = fmaf(c.x, m.x, -s.x * r.x);
    oii.y = fmaf(c.y, m.y, -s.y * r.y);
    oii.z = fmaf(c.z, m.z, -s.z * r.z);
    oii.w = fmaf(c.w, m.w, -s.w * r.w);

    out_re[u] = orr;
    out_im[u] = oii;
}

extern "C" void kernel_launch(void* const* d_in, const int* in_sizes, int n_in,
                              void* d_out, int out_size) {
    // metadata order: state_re, state_im, weights — but be robust to the small
    // (384-element) weights tensor landing in any slot.
    const float* sre = nullptr;
    const float* sim = nullptr;
    const float* w   = nullptr;
    for (int i = 0; i < n_in; i++) {
        if (in_sizes[i] == NBLOCKS * NQ) { w = (const float*)d_in[i]; }
        else if (!sre)                   { sre = (const float*)d_in[i]; }
        else                             { sim = (const float*)d_in[i]; }
    }

    float* out = (float*)d_out;           // [0, NELEM) real, [NELEM, 2*NELEM) imag

    phase_table_kernel<<<TABLE / 256, 256>>>(w);

    const int n4 = NELEM / 4;             // 16777216
    apply_kernel<<<n4 / 256, 256>>>((const float4*)sre,
                                    (const float4*)sim,
                                    (float4*)out,
                                    (float4*)(out + NELEM));
}

// round 2
// speedup vs baseline: 1.0014x; 1.0014x over previous
#include <cuda_runtime.h>

// Rz_layer: out = exp(-0.5i * phase(block, d)) * (re + i*im)
//   phase(blk, d) = sum_q w[blk][q] * (1 - 2*bit_q(d)),  bit_q = (d >> (NQ-1-q)) & 1
//   E(d) = exp(-i*phase/2) factorizes:  E(d) = E_hi[d>>6] * E_lo[d&63]
//     E_hi from qubits 0..5 (d bits 11..6), E_lo from qubits 6..11 (d bits 5..0)
//   out = E * state:  out_re = E.re*r - E.im*m ; out_im = E.re*m + E.im*r
//
// Shapes: state (256, 32, 2, 4096) fp32; weights (32, 12) fp32.
// Output: (2, 256, 32, 2, 4096) fp32 -> real plane then imag plane.

#define NQ       12
#define DIM      4096
#define NBLOCKS  32
#define DC       2
#define BATCH    256
#define NELEM    (BATCH * NBLOCKS * DC * DIM)   // 67108864

// 32 KB of complex partial-product tables (L1-resident in apply kernel).
// Layout: g_hi[blk*64 + j], g_lo[blk*64 + j], each float2 = (re, im) of exp(-i*angle).
__device__ float2 g_hi[NBLOCKS * 64];
__device__ float2 g_lo[NBLOCKS * 64];

// ---------------------------------------------------------------------------
// Kernel 1: build hi/lo partial-product tables. 4096 threads, 4096 sincos.
// idx: [blk(5) | half(1) | j(6)]  -> half=0 writes g_hi, half=1 writes g_lo
// ---------------------------------------------------------------------------
__global__ void factor_kernel(const float* __restrict__ w) {
    int idx = blockIdx.x * blockDim.x + threadIdx.x;   // < 4096
    int blk  = idx >> 7;
    int half = (idx >> 6) & 1;
    int j    = idx & 63;
    int qoff = half ? 6 : 0;

    float angle = 0.0f;
#pragma unroll
    for (int q = 0; q < 6; q++) {
        // bit for this qubit within the 6-bit group
        float sign = ((j >> (5 - q)) & 1) ? -0.5f : 0.5f;
        angle = fmaf(__ldg(&w[blk * NQ + qoff + q]), sign, angle);
    }
    float s, c;
    sincosf(angle, &s, &c);                 // accurate; only 4096 calls
    float2 e = make_float2(c, -s);          // exp(-i*angle)
    if (half) g_lo[(blk << 6) + j] = e;
    else      g_hi[(blk << 6) + j] = e;
}

// ---------------------------------------------------------------------------
// Kernel 2: streaming complex rotation, float4-vectorized.
// Element layout (fp32 units): (((batch*32 + blk)*2 + dc)*4096 + d)
// float4 index u: d4 = u & 1023 ; blk = (u>>11)&31 ; d_base = 4*d4
//   hi entry:  g_hi[blk*64 + (d4>>4)]            (broadcast across 16 threads)
//   lo entries: g_lo[blk*64 + (d4&15)*4 + 0..3]  (two float4 loads)
// Table slice per CTA = 1 KB -> L1-resident. State uses streaming hints.
// ---------------------------------------------------------------------------
__device__ __forceinline__ float2 cmul(float2 a, float2 b) {
    float2 r;
    r.x = fmaf(a.x, b.x, -a.y * b.y);
    r.y = fmaf(a.x, b.y,  a.y * b.x);
    return r;
}

__global__ void __launch_bounds__(256)
apply_kernel(const float4* __restrict__ re,
             const float4* __restrict__ im,
             float4* __restrict__ out_re,
             float4* __restrict__ out_im) {
    int u = blockIdx.x * blockDim.x + threadIdx.x;   // float4 index, < NELEM/4

    int d4  = u & 1023;
    int blk = (u >> 11) & 31;

    float2 eh = g_hi[(blk << 6) + (d4 >> 4)];

    // two float4 = four float2 lo entries (consecutive)
    const float4* lo4 = reinterpret_cast<const float4*>(g_lo);
    int lo_base = (blk << 5) + ((d4 & 15) << 1);     // float4 units
    float4 lo01 = __ldg(&lo4[lo_base]);
    float4 lo23 = __ldg(&lo4[lo_base + 1]);

    float2 E0 = cmul(eh, make_float2(lo01.x, lo01.y));
    float2 E1 = cmul(eh, make_float2(lo01.z, lo01.w));
    float2 E2 = cmul(eh, make_float2(lo23.x, lo23.y));
    float2 E3 = cmul(eh, make_float2(lo23.z, lo23.w));

    float4 r = __ldcs(&re[u]);       // streaming: no reuse, evict-first
    float4 m = __ldcs(&im[u]);

    float4 orr, oii;
    orr.x = fmaf(E0.x, r.x, -E0.y * m.x);
    oii.x = fmaf(E0.x, m.x,  E0.y * r.x);
    orr.y = fmaf(E1.x, r.y, -E1.y * m.y);
    oii.y = fmaf(E1.x, m.y,  E1.y * r.y);
    orr.z = fmaf(E2.x, r.z, -E2.y * m.z);
    oii.z = fmaf(E2.x, m.z,  E2.y * r.z);
    orr.w = fmaf(E3.x, r.w, -E3.y * m.w);
    oii.w = fmaf(E3.x, m.w,  E3.y * r.w);

    __stcs(&out_re[u], orr);
    __stcs(&out_im[u], oii);
}

extern "C" void kernel_launch(void* const* d_in, const int* in_sizes, int n_in,
                              void* d_out, int out_size) {
    // metadata order: state_re, state_im, weights — robust to the small
    // (384-element) weights tensor landing in any slot.
    const float* sre = nullptr;
    const float* sim = nullptr;
    const float* w   = nullptr;
    for (int i = 0; i < n_in; i++) {
        if (in_sizes[i] == NBLOCKS * NQ) { w = (const float*)d_in[i]; }
        else if (!sre)                   { sre = (const float*)d_in[i]; }
        else                             { sim = (const float*)d_in[i]; }
    }

    float* out = (float*)d_out;        // [0, NELEM) real, [NELEM, 2*NELEM) imag

    factor_kernel<<<16, 256>>>(w);

    const int n4 = NELEM / 4;          // 16777216
    apply_kernel<<<n4 / 256, 256>>>((const float4*)sre,
                                    (const float4*)sim,
                                    (float4*)out,
                                    (float4*)(out + NELEM));
}

// round 3
// speedup vs baseline: 1.0113x; 1.0098x over previous
#include <cuda_runtime.h>

// Rz_layer, fully fused single kernel.
//   out = exp(-0.5i * phase(blk, d)) * (re + i*im)
//   phase(blk, d) = sum_q w[blk][q] * (1 - 2*bit_q(d)),  bit_q = (d >> (NQ-1-q)) & 1
//   E(d) = exp(-i*phase/2) = E_hi[d>>6] * E_lo[d&63]
//     E_hi from qubits 0..5 (d bits 11..6), E_lo from qubits 6..11 (d bits 5..0)
//   out_re = E.re*r - E.im*m ; out_im = E.re*m + E.im*r
//
// Shapes: state (256, 32, 2, 4096) fp32; weights (32, 12) fp32.
// Output: (2, 256, 32, 2, 4096) fp32 -> real plane then imag plane.
//
// Each CTA: 256 threads handle 256 consecutive float4 = 1024 consecutive d
// inside one (batch, blk, dc) slice. Needed factor-table slice: 16 hi entries
// + 64 lo entries -> built in 640 B of smem (80 sincos per CTA, hidden under
// the memory-bound stream).

#define NQ       12
#define DIM      4096
#define NBLOCKS  32
#define DC       2
#define BATCH    256
#define NELEM    (BATCH * NBLOCKS * DC * DIM)   // 67108864

__device__ __forceinline__ float2 cmul(float2 a, float2 b) {
    float2 r;
    r.x = fmaf(a.x, b.x, -a.y * b.y);
    r.y = fmaf(a.x, b.y,  a.y * b.x);
    return r;
}

__global__ void __launch_bounds__(256)
rz_fused_kernel(const float*  __restrict__ w,
                const float4* __restrict__ re,
                const float4* __restrict__ im,
                float4*       __restrict__ out_re,
                float4*       __restrict__ out_im) {
    __shared__ float2 s_hi[16];   // E_hi for this CTA's 16 (d>>6) values
    __shared__ float2 s_lo[64];   // E_lo for all 64 (d&63) values

    const int tid    = threadIdx.x;
    const int u_base = blockIdx.x << 8;          // first float4 index of CTA
    const int u      = u_base + tid;

    const int blk     = (u_base >> 11) & 31;     // same for whole CTA
    const int hi_base = (u_base & 1023) >> 4;    // 0/16/32/48 within the slice

    // ---- build per-CTA factor tables (80 sincos) ----
    if (tid < 16) {
        int j = hi_base + tid;                   // the d>>6 value
        float angle = 0.0f;
#pragma unroll
        for (int q = 0; q < 6; q++) {
            float sign = ((j >> (5 - q)) & 1) ? -0.5f : 0.5f;
            angle = fmaf(__ldg(&w[blk * NQ + q]), sign, angle);
        }
        float s, c;
        sincosf(angle, &s, &c);
        s_hi[tid] = make_float2(c, -s);          // exp(-i*angle)
    } else if (tid >= 64 && tid < 128) {
        int j = tid - 64;                        // the d&63 value
        float angle = 0.0f;
#pragma unroll
        for (int q = 0; q < 6; q++) {
            float sign = ((j >> (5 - q)) & 1) ? -0.5f : 0.5f;
            angle = fmaf(__ldg(&w[blk * NQ + 6 + q]), sign, angle);
        }
        float s, c;
        sincosf(angle, &s, &c);
        s_lo[j] = make_float2(c, -s);
    }
    __syncthreads();

    // ---- streaming complex rotation ----
    // d = 4*(u_base + tid); d>>6 = hi_base + (tid>>4); d&63 = (tid&15)*4 + 0..3
    float2 eh = s_hi[tid >> 4];

    const float4* lo4 = reinterpret_cast<const float4*>(s_lo);
    int lb = (tid & 15) << 1;                    // float4 units into s_lo
    float4 lo01 = lo4[lb];
    float4 lo23 = lo4[lb + 1];

    float2 E0 = cmul(eh, make_float2(lo01.x, lo01.y));
    float2 E1 = cmul(eh, make_float2(lo01.z, lo01.w));
    float2 E2 = cmul(eh, make_float2(lo23.x, lo23.y));
    float2 E3 = cmul(eh, make_float2(lo23.z, lo23.w));

    float4 r = __ldcs(&re[u]);                   // streaming, evict-first
    float4 m = __ldcs(&im[u]);

    float4 orr, oii;
    orr.x = fmaf(E0.x, r.x, -E0.y * m.x);
    oii.x = fmaf(E0.x, m.x,  E0.y * r.x);
    orr.y = fmaf(E1.x, r.y, -E1.y * m.y);
    oii.y = fmaf(E1.x, m.y,  E1.y * r.y);
    orr.z = fmaf(E2.x, r.z, -E2.y * m.z);
    oii.z = fmaf(E2.x, m.z,  E2.y * r.z);
    orr.w = fmaf(E3.x, r.w, -E3.y * m.w);
    oii.w = fmaf(E3.x, m.w,  E3.y * r.w);

    __stcs(&out_re[u], orr);
    __stcs(&out_im[u], oii);
}

extern "C" void kernel_launch(void* const* d_in, const int* in_sizes, int n_in,
                              void* d_out, int out_size) {
    // metadata order: state_re, state_im, weights — robust to the small
    // (384-element) weights tensor landing in any slot.
    const float* sre = nullptr;
    const float* sim = nullptr;
    const float* w   = nullptr;
    for (int i = 0; i < n_in; i++) {
        if (in_sizes[i] == NBLOCKS * NQ) { w = (const float*)d_in[i]; }
        else if (!sre)                   { sre = (const float*)d_in[i]; }
        else                             { sim = (const float*)d_in[i]; }
    }

    float* out = (float*)d_out;        // [0, NELEM) real, [NELEM, 2*NELEM) imag

    const int n4 = NELEM / 4;          // 16777216
    rz_fused_kernel<<<n4 / 256, 256>>>(w,
                                       (const float4*)sre,
                                       (const float4*)sim,
                                       (float4*)out,
                                       (float4*)(out + NELEM));
}